// round 1
// baseline (speedup 1.0000x reference)
#include <cuda_runtime.h>
#include <math.h>

// ---------------------------------------------------------------------------
// Problem constants
// B=2, T=24, H=256, W=256, N=512, HIDDEN=256
// conv1: 7x7x3->64 s2 SAME (pad_lo=2)  -> 128x128
// conv2: 3x3x64->128 s2 SAME (pad_lo=0)-> 64x64
// conv3: 3x3x128->256 s2 SAME (pad_lo=0)-> 32x32
// ---------------------------------------------------------------------------

__device__ float g_feat1[2 * 24 * 128 * 128 * 64];   // 201 MB
__device__ float g_feat2[2 * 24 * 64 * 64 * 128];    // 100 MB
__device__ float g_feat3[2 * 24 * 32 * 32 * 256];    //  50 MB
__device__ float g_q[2 * 512 * 256];                 //   1 MB
__device__ float g_corr[2 * 24 * 512 * 1024];        // 100 MB  [bt][n][hw]

// ---------------------------------------------------------------------------
// conv1: 7x7, stride 2, pad_lo=2, Cin=3, Cout=64. One thread = one output
// pixel, 64 accumulators. Weights (9408 f) + bias in smem.
// ---------------------------------------------------------------------------
__global__ void __launch_bounds__(128) conv1_kernel(
    const float* __restrict__ video,
    const float* __restrict__ w,
    const float* __restrict__ bias)
{
    __shared__ float sw[7 * 7 * 3 * 64 + 64];
    for (int i = threadIdx.x; i < 7 * 7 * 3 * 64; i += 128) sw[i] = w[i];
    if (threadIdx.x < 64) sw[9408 + threadIdx.x] = bias[threadIdx.x];
    __syncthreads();

    int p  = blockIdx.x * 128 + threadIdx.x;   // [0, 2*24*128*128)
    int x  = p & 127;
    int y  = (p >> 7) & 127;
    int bt = p >> 14;

    float acc[64];
#pragma unroll
    for (int c = 0; c < 64; c++) acc[c] = sw[9408 + c];

    const float* vb = video + (size_t)bt * (256 * 256 * 3);
    const float inv255 = 1.0f / 255.0f;

#pragma unroll 1
    for (int dy = 0; dy < 7; dy++) {
        int iy = 2 * y + dy - 2;
        if ((unsigned)iy >= 256u) continue;
#pragma unroll 1
        for (int dx = 0; dx < 7; dx++) {
            int ix = 2 * x + dx - 2;
            if ((unsigned)ix >= 256u) continue;
            const float* vp = vb + ((size_t)iy * 256 + ix) * 3;
#pragma unroll
            for (int ci = 0; ci < 3; ci++) {
                float v = vp[ci] * inv255;
                const float4* w4 =
                    reinterpret_cast<const float4*>(&sw[((dy * 7 + dx) * 3 + ci) * 64]);
#pragma unroll
                for (int k = 0; k < 16; k++) {
                    float4 wv = w4[k];
                    acc[4 * k + 0] = fmaf(v, wv.x, acc[4 * k + 0]);
                    acc[4 * k + 1] = fmaf(v, wv.y, acc[4 * k + 1]);
                    acc[4 * k + 2] = fmaf(v, wv.z, acc[4 * k + 2]);
                    acc[4 * k + 3] = fmaf(v, wv.w, acc[4 * k + 3]);
                }
            }
        }
    }

    float4* op = reinterpret_cast<float4*>(&g_feat1[(size_t)p * 64]);
#pragma unroll
    for (int k = 0; k < 16; k++) {
        float4 o;
        o.x = fmaxf(acc[4 * k + 0], 0.0f);
        o.y = fmaxf(acc[4 * k + 1], 0.0f);
        o.z = fmaxf(acc[4 * k + 2], 0.0f);
        o.w = fmaxf(acc[4 * k + 3], 0.0f);
        op[k] = o;
    }
}

// ---------------------------------------------------------------------------
// Generic 3x3 stride-2 conv, pad_lo=0, pad_hi=1. Output-channel chunk CC per
// block (blockIdx.y). One thread = one output pixel, CC accumulators.
// Weight slice (9*CIN*CC floats) in dynamic smem.
// ---------------------------------------------------------------------------
template <int CIN, int COUT, int CC, int HIN, int WIN, int HOUT, int WOUT>
__global__ void __launch_bounds__(256) conv3x3_kernel(
    const float* __restrict__ in,
    const float* __restrict__ w,
    const float* __restrict__ bias,
    float* __restrict__ out)
{
    extern __shared__ float sw[];
    __shared__ float sb[CC];
    const int WSZ = 9 * CIN * CC;
    const int cobase = blockIdx.y * CC;

    for (int i = threadIdx.x; i < WSZ; i += 256) {
        int r = i / CC, cc = i - r * CC;
        sw[i] = w[r * COUT + cobase + cc];
    }
    if (threadIdx.x < CC) sb[threadIdx.x] = bias[cobase + threadIdx.x];
    __syncthreads();

    int p  = blockIdx.x * 256 + threadIdx.x;
    int x  = p % WOUT;
    int y  = (p / WOUT) % HOUT;
    int bt = p / (WOUT * HOUT);

    float acc[CC];
#pragma unroll
    for (int c = 0; c < CC; c++) acc[c] = sb[c];

#pragma unroll
    for (int dy = 0; dy < 3; dy++) {
        int iy = 2 * y + dy;
        if (iy >= HIN) continue;
#pragma unroll
        for (int dx = 0; dx < 3; dx++) {
            int ix = 2 * x + dx;
            if (ix >= WIN) continue;
            const float* ip = in + (((size_t)bt * HIN + iy) * WIN + ix) * CIN;
            const float* wr = sw + (dy * 3 + dx) * CIN * CC;
#pragma unroll 8
            for (int ci = 0; ci < CIN; ci++) {
                float v = __ldg(ip + ci);
                const float4* w4 = reinterpret_cast<const float4*>(wr + ci * CC);
#pragma unroll
                for (int k = 0; k < CC / 4; k++) {
                    float4 wv = w4[k];
                    acc[4 * k + 0] = fmaf(v, wv.x, acc[4 * k + 0]);
                    acc[4 * k + 1] = fmaf(v, wv.y, acc[4 * k + 1]);
                    acc[4 * k + 2] = fmaf(v, wv.z, acc[4 * k + 2]);
                    acc[4 * k + 3] = fmaf(v, wv.w, acc[4 * k + 3]);
                }
            }
        }
    }

    float4* op = reinterpret_cast<float4*>(out + (size_t)p * COUT + cobase);
#pragma unroll
    for (int k = 0; k < CC / 4; k++) {
        float4 o;
        o.x = fmaxf(acc[4 * k + 0], 0.0f);
        o.y = fmaxf(acc[4 * k + 1], 0.0f);
        o.z = fmaxf(acc[4 * k + 2], 0.0f);
        o.w = fmaxf(acc[4 * k + 3], 0.0f);
        op[k] = o;
    }
}

// ---------------------------------------------------------------------------
// Bilinear feature sampling at query points. One block per (b,n), thread=channel.
// ---------------------------------------------------------------------------
__global__ void __launch_bounds__(256) sample_kernel(const float* __restrict__ qp)
{
    int bn = blockIdx.x;               // 0..1023 ; b = bn>>9, n = bn&511
    float q0 = qp[bn * 3 + 0];
    float q1 = qp[bn * 3 + 1];
    float q2 = qp[bn * 3 + 2];

    int t = (int)(q0 * 23.0f);
    t = min(max(t, 0), 23);
    float yf = q1 * 31.0f;
    float xf = q2 * 31.0f;
    int y0 = min(max((int)floorf(yf), 0), 31);
    int y1 = min(y0 + 1, 31);
    int x0 = min(max((int)floorf(xf), 0), 31);
    int x1 = min(x0 + 1, 31);
    float wy1 = yf - (float)y0, wy0 = 1.0f - wy1;
    float wx1 = xf - (float)x0, wx0 = 1.0f - wx1;

    int b = bn >> 9;
    const float* f = g_feat3 + (size_t)(b * 24 + t) * 1024 * 256;
    int c = threadIdx.x;
    float f00 = f[(size_t)(y0 * 32 + x0) * 256 + c];
    float f01 = f[(size_t)(y0 * 32 + x1) * 256 + c];
    float f10 = f[(size_t)(y1 * 32 + x0) * 256 + c];
    float f11 = f[(size_t)(y1 * 32 + x1) * 256 + c];
    float f0 = f00 * wx0 + f01 * wx1;
    float f1 = f10 * wx0 + f11 * wx1;
    g_q[(size_t)bn * 256 + c] = f0 * wy0 + f1 * wy1;
}

// ---------------------------------------------------------------------------
// corr[bt][n][hw] = (Q[b][n][:] . X[bt][hw][:]) / 16
// Tiled fp32 GEMM: 64(n) x 64(hw), K-tile 32, 256 threads, 4x4 microtile.
// Smem stored k-major (transposed on load) for conflict-free LDS.128.
// ---------------------------------------------------------------------------
__global__ void __launch_bounds__(256) corr_gemm_kernel()
{
    __shared__ float As[32][68];
    __shared__ float Bs[32][68];

    int bt = blockIdx.z;
    int b  = bt / 24;
    const float* A = g_q + (size_t)b * 512 * 256;        // [n][c]
    const float* X = g_feat3 + (size_t)bt * 1024 * 256;  // [hw][c]
    int n0  = blockIdx.y * 64;
    int hw0 = blockIdx.x * 64;

    int tid = threadIdx.x;
    int tx = tid & 15;    // hw dir
    int ty = tid >> 4;    // n dir

    float acc[4][4];
#pragma unroll
    for (int i = 0; i < 4; i++)
#pragma unroll
        for (int j = 0; j < 4; j++) acc[i][j] = 0.0f;

    for (int kt = 0; kt < 256; kt += 32) {
#pragma unroll
        for (int u0 = 0; u0 < 2; u0++) {
            int u   = tid * 2 + u0;
            int row = u >> 3;
            int kq  = u & 7;
            float4 av = *reinterpret_cast<const float4*>(
                &A[(size_t)(n0 + row) * 256 + kt + kq * 4]);
            As[kq * 4 + 0][row] = av.x;
            As[kq * 4 + 1][row] = av.y;
            As[kq * 4 + 2][row] = av.z;
            As[kq * 4 + 3][row] = av.w;
            float4 bv = *reinterpret_cast<const float4*>(
                &X[(size_t)(hw0 + row) * 256 + kt + kq * 4]);
            Bs[kq * 4 + 0][row] = bv.x;
            Bs[kq * 4 + 1][row] = bv.y;
            Bs[kq * 4 + 2][row] = bv.z;
            Bs[kq * 4 + 3][row] = bv.w;
        }
        __syncthreads();
#pragma unroll
        for (int k = 0; k < 32; k++) {
            float4 a  = *reinterpret_cast<const float4*>(&As[k][ty * 4]);
            float4 bb = *reinterpret_cast<const float4*>(&Bs[k][tx * 4]);
            acc[0][0] = fmaf(a.x, bb.x, acc[0][0]);
            acc[0][1] = fmaf(a.x, bb.y, acc[0][1]);
            acc[0][2] = fmaf(a.x, bb.z, acc[0][2]);
            acc[0][3] = fmaf(a.x, bb.w, acc[0][3]);
            acc[1][0] = fmaf(a.y, bb.x, acc[1][0]);
            acc[1][1] = fmaf(a.y, bb.y, acc[1][1]);
            acc[1][2] = fmaf(a.y, bb.z, acc[1][2]);
            acc[1][3] = fmaf(a.y, bb.w, acc[1][3]);
            acc[2][0] = fmaf(a.z, bb.x, acc[2][0]);
            acc[2][1] = fmaf(a.z, bb.y, acc[2][1]);
            acc[2][2] = fmaf(a.z, bb.z, acc[2][2]);
            acc[2][3] = fmaf(a.z, bb.w, acc[2][3]);
            acc[3][0] = fmaf(a.w, bb.x, acc[3][0]);
            acc[3][1] = fmaf(a.w, bb.y, acc[3][1]);
            acc[3][2] = fmaf(a.w, bb.z, acc[3][2]);
            acc[3][3] = fmaf(a.w, bb.w, acc[3][3]);
        }
        __syncthreads();
    }

    float* C = g_corr + (size_t)bt * 512 * 1024;
#pragma unroll
    for (int i = 0; i < 4; i++) {
        float4 o;
        o.x = acc[i][0] * 0.0625f;
        o.y = acc[i][1] * 0.0625f;
        o.z = acc[i][2] * 0.0625f;
        o.w = acc[i][3] * 0.0625f;
        *reinterpret_cast<float4*>(
            &C[(size_t)(n0 + ty * 4 + i) * 1024 + hw0 + tx * 4]) = o;
    }
}

// ---------------------------------------------------------------------------
// Fused softmax(corr*10) expectation + occlusion. One warp per (b,n,t) row
// of 1024 corr values. Output: pred [B,N,T,2] then occlusion [B,N,T].
// ---------------------------------------------------------------------------
__global__ void __launch_bounds__(256) finalize_kernel(float* __restrict__ out)
{
    int gwarp = (blockIdx.x * 256 + threadIdx.x) >> 5;  // 0..24575 = bt*512+n
    int lane  = threadIdx.x & 31;

    const float* c = g_corr + (size_t)gwarp * 1024;
    float v[32];
    float m = -1e30f;
#pragma unroll
    for (int i = 0; i < 8; i++) {
        float4 t4 = *reinterpret_cast<const float4*>(&c[i * 128 + lane * 4]);
        v[i * 4 + 0] = t4.x;
        v[i * 4 + 1] = t4.y;
        v[i * 4 + 2] = t4.z;
        v[i * 4 + 3] = t4.w;
        m = fmaxf(m, fmaxf(fmaxf(t4.x, t4.y), fmaxf(t4.z, t4.w)));
    }
#pragma unroll
    for (int o = 16; o > 0; o >>= 1)
        m = fmaxf(m, __shfl_xor_sync(0xffffffffu, m, o));

    float s = 0.0f, sx = 0.0f, sy = 0.0f;
#pragma unroll
    for (int i = 0; i < 8; i++) {
#pragma unroll
        for (int j = 0; j < 4; j++) {
            int idx = i * 128 + lane * 4 + j;
            float e = __expf(10.0f * (v[i * 4 + j] - m));
            s  += e;
            sx += e * (float)(idx & 31);   // w coordinate
            sy += e * (float)(idx >> 5);   // h coordinate
        }
    }
#pragma unroll
    for (int o = 16; o > 0; o >>= 1) {
        s  += __shfl_xor_sync(0xffffffffu, s, o);
        sx += __shfl_xor_sync(0xffffffffu, sx, o);
        sy += __shfl_xor_sync(0xffffffffu, sy, o);
    }

    if (lane == 0) {
        int bt = gwarp >> 9;
        int n  = gwarp & 511;
        int b  = bt / 24;
        int t  = bt - b * 24;
        int o  = (b * 512 + n) * 24 + t;
        float inv = 8.0f / s;               // * (W/fW) = *8
        out[2 * o + 0] = sx * inv;
        out[2 * o + 1] = sy * inv;
        out[2 * 24576 + o] = 1.0f / (1.0f + __expf(m));   // sigmoid(-max)
    }
}

// ---------------------------------------------------------------------------
// Launch
// ---------------------------------------------------------------------------
extern "C" void kernel_launch(void* const* d_in, const int* in_sizes, int n_in,
                              void* d_out, int out_size)
{
    const float* video = (const float*)d_in[0];
    const float* qp    = (const float*)d_in[1];
    const float* w1    = (const float*)d_in[2];
    const float* b1    = (const float*)d_in[3];
    const float* w2    = (const float*)d_in[4];
    const float* b2    = (const float*)d_in[5];
    const float* w3    = (const float*)d_in[6];
    const float* b3    = (const float*)d_in[7];

    float *f1, *f2, *f3;
    cudaGetSymbolAddress((void**)&f1, g_feat1);
    cudaGetSymbolAddress((void**)&f2, g_feat2);
    cudaGetSymbolAddress((void**)&f3, g_feat3);

    const int SMEM_C2 = 9 * 64 * 64 * 4;    // 147456 B
    const int SMEM_C3 = 9 * 128 * 32 * 4;   // 147456 B
    cudaFuncSetAttribute((const void*)conv3x3_kernel<64, 128, 64, 128, 128, 64, 64>,
                         cudaFuncAttributeMaxDynamicSharedMemorySize, SMEM_C2);
    cudaFuncSetAttribute((const void*)conv3x3_kernel<128, 256, 32, 64, 64, 32, 32>,
                         cudaFuncAttributeMaxDynamicSharedMemorySize, SMEM_C3);

    // conv1: 2*24*128*128 = 786432 outputs / 128 = 6144 blocks
    conv1_kernel<<<6144, 128>>>(video, w1, b1);

    // conv2: 2*24*64*64 = 196608 / 256 = 768 blocks x 2 co-chunks
    conv3x3_kernel<64, 128, 64, 128, 128, 64, 64>
        <<<dim3(768, 2, 1), 256, SMEM_C2>>>(f1, w2, b2, f2);

    // conv3: 2*24*32*32 = 49152 / 256 = 192 blocks x 8 co-chunks
    conv3x3_kernel<128, 256, 32, 64, 64, 32, 32>
        <<<dim3(192, 8, 1), 256, SMEM_C3>>>(f2, w3, b3, f3);

    // feature sampling: one block per (b,n)
    sample_kernel<<<1024, 256>>>(qp);

    // correlation GEMM: per bt, 16 hw-tiles x 8 n-tiles
    corr_gemm_kernel<<<dim3(16, 8, 48), 256>>>();

    // softmax + expectation + occlusion: 24576 warps
    finalize_kernel<<<3072, 256>>>((float*)d_out);
}

// round 4
// speedup vs baseline: 3.7964x; 3.7964x over previous
#include <cuda_runtime.h>
#include <cuda_bf16.h>
#include <math.h>
#include <stdint.h>

// ---------------------------------------------------------------------------
// Problem constants
// B=2, T=24, H=256, W=256, N=512, HIDDEN=256
// conv1: 7x7x3->64 s2 SAME (pad_lo=2)  -> 128x128   (fp32 direct)
// conv2: 3x3x64->128 s2 (pad_lo=0)     -> 64x64     (mma.sync bf16x3 implicit GEMM)
// conv3: 3x3x128->256 s2 (pad_lo=0)    -> 32x32     (mma.sync bf16x3 implicit GEMM)
// corr : [48] 512x1024x256 GEMM                      (mma.sync bf16x3)
// ---------------------------------------------------------------------------

__device__ float g_feat1[2 * 24 * 128 * 128 * 64];   // 201 MB
__device__ float g_feat2[2 * 24 * 64 * 64 * 128];    // 100 MB
__device__ float g_feat3[2 * 24 * 32 * 32 * 256];    //  50 MB
__device__ float g_q[2 * 512 * 256];                 //   1 MB
__device__ float g_corr[2 * 24 * 512 * 1024];        // 100 MB  [bt][n][hw]
__device__ float g_wt2[128 * 576];                   // w2 transposed [cout][k]
__device__ float g_wt3[256 * 1152];                  // w3 transposed [cout][k]

// ---------------------------------------------------------------------------
// helpers
// ---------------------------------------------------------------------------
__device__ __forceinline__ uint32_t smem_u32(const void* p) {
    uint32_t a;
    asm("{ .reg .u64 t; cvta.to.shared.u64 t, %1; cvt.u32.u64 %0, t; }"
        : "=r"(a) : "l"(p));
    return a;
}

__device__ __forceinline__ void ldmx4(uint32_t* r, uint32_t addr) {
    asm volatile(
        "ldmatrix.sync.aligned.m8n8.x4.shared.b16 {%0,%1,%2,%3}, [%4];"
        : "=r"(r[0]), "=r"(r[1]), "=r"(r[2]), "=r"(r[3]) : "r"(addr));
}

__device__ __forceinline__ void mma_bf16(float* d, const uint32_t* a,
                                         const uint32_t* b) {
    asm volatile(
        "mma.sync.aligned.m16n8k16.row.col.f32.bf16.bf16.f32 "
        "{%0,%1,%2,%3}, {%4,%5,%6,%7}, {%8,%9}, {%0,%1,%2,%3};"
        : "+f"(d[0]), "+f"(d[1]), "+f"(d[2]), "+f"(d[3])
        : "r"(a[0]), "r"(a[1]), "r"(a[2]), "r"(a[3]), "r"(b[0]), "r"(b[1]));
}

// split one float4 into bf16-hi and bf16-lo pairs, write 8B each to smem
__device__ __forceinline__ void split_store(char* hi, char* lo, float4 v) {
    __nv_bfloat162 h01 = __floats2bfloat162_rn(v.x, v.y);
    __nv_bfloat162 h23 = __floats2bfloat162_rn(v.z, v.w);
    float hx = __bfloat162float(h01.x), hy = __bfloat162float(h01.y);
    float hz = __bfloat162float(h23.x), hw = __bfloat162float(h23.y);
    __nv_bfloat162 l01 = __floats2bfloat162_rn(v.x - hx, v.y - hy);
    __nv_bfloat162 l23 = __floats2bfloat162_rn(v.z - hz, v.w - hw);
    uint2 hv = make_uint2(*reinterpret_cast<uint32_t*>(&h01),
                          *reinterpret_cast<uint32_t*>(&h23));
    uint2 lv = make_uint2(*reinterpret_cast<uint32_t*>(&l01),
                          *reinterpret_cast<uint32_t*>(&l23));
    *reinterpret_cast<uint2*>(hi) = hv;
    *reinterpret_cast<uint2*>(lo) = lv;
}

// smem tile geometry: 128 rows x 32 bf16, row stride 80 B (16B pad -> cf-free)
#define RS   80
#define MATB (128 * RS)    // 10240 B per matrix
#define BUFB (4 * MATB)    // A_hi | A_lo | B_hi | B_lo
#define DSMEM (2 * BUFB)   // double buffered: 81920 B

// ---------------------------------------------------------------------------
// conv1: 7x7, stride 2, pad_lo=2, Cin=3, Cout=64 (fp32 direct)
// ---------------------------------------------------------------------------
__global__ void __launch_bounds__(128) conv1_kernel(
    const float* __restrict__ video,
    const float* __restrict__ w,
    const float* __restrict__ bias)
{
    __shared__ float sw[7 * 7 * 3 * 64 + 64];
    for (int i = threadIdx.x; i < 7 * 7 * 3 * 64; i += 128) sw[i] = w[i];
    if (threadIdx.x < 64) sw[9408 + threadIdx.x] = bias[threadIdx.x];
    __syncthreads();

    int p  = blockIdx.x * 128 + threadIdx.x;
    int x  = p & 127;
    int y  = (p >> 7) & 127;
    int bt = p >> 14;

    float acc[64];
#pragma unroll
    for (int c = 0; c < 64; c++) acc[c] = sw[9408 + c];

    const float* vb = video + (size_t)bt * (256 * 256 * 3);
    const float inv255 = 1.0f / 255.0f;

#pragma unroll 1
    for (int dy = 0; dy < 7; dy++) {
        int iy = 2 * y + dy - 2;
        if ((unsigned)iy >= 256u) continue;
#pragma unroll 1
        for (int dx = 0; dx < 7; dx++) {
            int ix = 2 * x + dx - 2;
            if ((unsigned)ix >= 256u) continue;
            const float* vp = vb + ((size_t)iy * 256 + ix) * 3;
#pragma unroll
            for (int ci = 0; ci < 3; ci++) {
                float v = vp[ci] * inv255;
                const float4* w4 =
                    reinterpret_cast<const float4*>(&sw[((dy * 7 + dx) * 3 + ci) * 64]);
#pragma unroll
                for (int k = 0; k < 16; k++) {
                    float4 wv = w4[k];
                    acc[4 * k + 0] = fmaf(v, wv.x, acc[4 * k + 0]);
                    acc[4 * k + 1] = fmaf(v, wv.y, acc[4 * k + 1]);
                    acc[4 * k + 2] = fmaf(v, wv.z, acc[4 * k + 2]);
                    acc[4 * k + 3] = fmaf(v, wv.w, acc[4 * k + 3]);
                }
            }
        }
    }

    float4* op = reinterpret_cast<float4*>(&g_feat1[(size_t)p * 64]);
#pragma unroll
    for (int k = 0; k < 16; k++) {
        float4 o;
        o.x = fmaxf(acc[4 * k + 0], 0.0f);
        o.y = fmaxf(acc[4 * k + 1], 0.0f);
        o.z = fmaxf(acc[4 * k + 2], 0.0f);
        o.w = fmaxf(acc[4 * k + 3], 0.0f);
        op[k] = o;
    }
}

// ---------------------------------------------------------------------------
// Weight transpose: w[k][cout] -> wt[cout][k]
// ---------------------------------------------------------------------------
__global__ void transpose_w_kernel(const float* __restrict__ w,
                                   float* __restrict__ wt, int K, int C)
{
    int i = blockIdx.x * 256 + threadIdx.x;
    if (i < K * C) {
        int k = i / C, c = i - k * C;
        wt[(size_t)c * K + k] = w[i];
    }
}

// ---------------------------------------------------------------------------
// Implicit-GEMM 3x3 s2 conv (pad_lo=0, pad_hi=1), mma.sync bf16 3-pass.
// Block tile 128(M pixels) x 128(N couts), K chunk 32. 8 warps (2M x 4N),
// warp tile 64x32. Double-buffered smem. 1 CTA/SM (reg-fat, no spill).
// ---------------------------------------------------------------------------
template <int CIN, int COUT, int HIN, int WIN, int HOUT, int WOUT>
__global__ void __launch_bounds__(256, 1) conv_mma_kernel(
    const float* __restrict__ in,
    const float* __restrict__ wt,     // [COUT][9*CIN]
    const float* __restrict__ bias,
    float* __restrict__ out)
{
    extern __shared__ char sm[];
    __shared__ float s_bias[128];

    const int K   = 9 * CIN;
    const int CPP = CIN / 32;
    const int NT  = 9 * CPP;

    int tid  = threadIdx.x;
    int lane = tid & 31;
    int wid  = tid >> 5;
    int wm   = wid & 1;
    int wn   = wid >> 1;
    int cobase = blockIdx.y * 128;

    if (tid < 128) s_bias[tid] = bias[cobase + tid];

    // fill indices: 2 threads per row, 16 floats each
    int fr = tid >> 1;
    int fo = (tid & 1) * 16;
    int p  = blockIdx.x * 128 + fr;
    int fx = p % WOUT;
    int fy = (p / WOUT) % HOUT;
    int fbt = p / (WOUT * HOUT);
    const float* wrow = wt + (size_t)(cobase + fr) * K + fo;

    uint32_t smb = smem_u32(sm);
    char* smc = sm;

    // ldmatrix per-lane offsets (bytes within one 128x32 matrix)
    int aoff = ((((lane >> 3) & 1) * 8 + (lane & 7)) * RS) + ((lane >> 4) * 8) * 2;
    int boff = (((lane >> 4) * 8 + (lane & 7)) * RS) + (((lane >> 3) & 1) * 8) * 2;

    float acc[4][4][4];
#pragma unroll
    for (int i = 0; i < 4; i++)
#pragma unroll
        for (int j = 0; j < 4; j++)
#pragma unroll
            for (int k = 0; k < 4; k++) acc[i][j][k] = 0.0f;

    float4 av[4], bv[4];

    auto LOAD = [&](int kt) {
        int pos = kt / CPP, ci0 = (kt - pos * CPP) * 32;
        int dy = pos / 3, dx = pos - dy * 3;
        int iy = 2 * fy + dy, ix = 2 * fx + dx;
        if (iy < HIN && ix < WIN) {
            const float4* s = reinterpret_cast<const float4*>(
                in + (((size_t)fbt * HIN + iy) * WIN + ix) * CIN + ci0 + fo);
            av[0] = s[0]; av[1] = s[1]; av[2] = s[2]; av[3] = s[3];
        } else {
            av[0] = av[1] = av[2] = av[3] = make_float4(0.f, 0.f, 0.f, 0.f);
        }
        const float4* w4 = reinterpret_cast<const float4*>(wrow + kt * 32);
        bv[0] = w4[0]; bv[1] = w4[1]; bv[2] = w4[2]; bv[3] = w4[3];
    };

    auto STORE = [&](int buf) {
        char* base = smc + buf * BUFB + fr * RS + fo * 2;
#pragma unroll
        for (int j = 0; j < 4; j++) {
            split_store(base + j * 8, base + MATB + j * 8, av[j]);
            split_store(base + 2 * MATB + j * 8, base + 3 * MATB + j * 8, bv[j]);
        }
    };

    auto COMPUTE = [&](int buf) {
        uint32_t ab = smb + buf * BUFB;
#pragma unroll
        for (int ks = 0; ks < 2; ks++) {
            uint32_t bh[8], bl[8];
#pragma unroll
            for (int q = 0; q < 2; q++) {
                uint32_t baddr = ab + 2 * MATB + boff + (wn * 32 + q * 16) * RS + ks * 32;
                ldmx4(&bh[4 * q], baddr);
                ldmx4(&bl[4 * q], baddr + MATB);
            }
#pragma unroll
            for (int mt = 0; mt < 4; mt++) {
                uint32_t af[4];
                uint32_t aaddr = ab + aoff + (wm * 64 + mt * 16) * RS + ks * 32;
                ldmx4(af, aaddr);
#pragma unroll
                for (int nt = 0; nt < 4; nt++) mma_bf16(acc[mt][nt], af, &bh[2 * nt]);
#pragma unroll
                for (int nt = 0; nt < 4; nt++) mma_bf16(acc[mt][nt], af, &bl[2 * nt]);
                ldmx4(af, aaddr + MATB);
#pragma unroll
                for (int nt = 0; nt < 4; nt++) mma_bf16(acc[mt][nt], af, &bh[2 * nt]);
            }
        }
    };

    LOAD(0);
    STORE(0);
    __syncthreads();
#pragma unroll 1
    for (int kt = 0; kt < NT; kt++) {
        if (kt + 1 < NT) LOAD(kt + 1);
        COMPUTE(kt & 1);
        if (kt + 1 < NT) {
            STORE((kt + 1) & 1);
            __syncthreads();
        }
    }

    // epilogue: bias + relu
    int mrow = blockIdx.x * 128 + wm * 64 + (lane >> 2);
    int cbase = wn * 32 + 2 * (lane & 3);
#pragma unroll
    for (int mt = 0; mt < 4; mt++) {
#pragma unroll
        for (int nt = 0; nt < 4; nt++) {
            int col = cbase + nt * 8;
            float b0 = s_bias[col], b1 = s_bias[col + 1];
            int r0 = mrow + mt * 16;
            float2 o0, o1;
            o0.x = fmaxf(acc[mt][nt][0] + b0, 0.f);
            o0.y = fmaxf(acc[mt][nt][1] + b1, 0.f);
            o1.x = fmaxf(acc[mt][nt][2] + b0, 0.f);
            o1.y = fmaxf(acc[mt][nt][3] + b1, 0.f);
            *reinterpret_cast<float2*>(out + (size_t)r0 * COUT + cobase + col) = o0;
            *reinterpret_cast<float2*>(out + (size_t)(r0 + 8) * COUT + cobase + col) = o1;
        }
    }
}

// ---------------------------------------------------------------------------
// corr GEMM: D[bt][n][hw] = Q[b][n][:] . X[bt][hw][:] / 16, mma.sync bf16 3x.
// ---------------------------------------------------------------------------
__global__ void __launch_bounds__(256, 1) corr_mma_kernel()
{
    extern __shared__ char sm[];

    int tid  = threadIdx.x;
    int lane = tid & 31;
    int wid  = tid >> 5;
    int wm   = wid & 1;
    int wn   = wid >> 1;

    int bt  = blockIdx.z;
    int b   = bt / 24;
    int n0  = blockIdx.y * 128;
    int hw0 = blockIdx.x * 128;

    int fr = tid >> 1;
    int fo = (tid & 1) * 16;
    const float* arow = g_q + ((size_t)b * 512 + n0 + fr) * 256 + fo;
    const float* brow = g_feat3 + ((size_t)bt * 1024 + hw0 + fr) * 256 + fo;

    uint32_t smb = smem_u32(sm);
    char* smc = sm;

    int aoff = ((((lane >> 3) & 1) * 8 + (lane & 7)) * RS) + ((lane >> 4) * 8) * 2;
    int boff = (((lane >> 4) * 8 + (lane & 7)) * RS) + (((lane >> 3) & 1) * 8) * 2;

    float acc[4][4][4];
#pragma unroll
    for (int i = 0; i < 4; i++)
#pragma unroll
        for (int j = 0; j < 4; j++)
#pragma unroll
            for (int k = 0; k < 4; k++) acc[i][j][k] = 0.0f;

    float4 av[4], bv[4];

    auto LOAD = [&](int kt) {
        const float4* s0 = reinterpret_cast<const float4*>(arow + kt * 32);
        av[0] = s0[0]; av[1] = s0[1]; av[2] = s0[2]; av[3] = s0[3];
        const float4* s1 = reinterpret_cast<const float4*>(brow + kt * 32);
        bv[0] = s1[0]; bv[1] = s1[1]; bv[2] = s1[2]; bv[3] = s1[3];
    };
    auto STORE = [&](int buf) {
        char* base = smc + buf * BUFB + fr * RS + fo * 2;
#pragma unroll
        for (int j = 0; j < 4; j++) {
            split_store(base + j * 8, base + MATB + j * 8, av[j]);
            split_store(base + 2 * MATB + j * 8, base + 3 * MATB + j * 8, bv[j]);
        }
    };
    auto COMPUTE = [&](int buf) {
        uint32_t ab = smb + buf * BUFB;
#pragma unroll
        for (int ks = 0; ks < 2; ks++) {
            uint32_t bh[8], bl[8];
#pragma unroll
            for (int q = 0; q < 2; q++) {
                uint32_t baddr = ab + 2 * MATB + boff + (wn * 32 + q * 16) * RS + ks * 32;
                ldmx4(&bh[4 * q], baddr);
                ldmx4(&bl[4 * q], baddr + MATB);
            }
#pragma unroll
            for (int mt = 0; mt < 4; mt++) {
                uint32_t af[4];
                uint32_t aaddr = ab + aoff + (wm * 64 + mt * 16) * RS + ks * 32;
                ldmx4(af, aaddr);
#pragma unroll
                for (int nt = 0; nt < 4; nt++) mma_bf16(acc[mt][nt], af, &bh[2 * nt]);
#pragma unroll
                for (int nt = 0; nt < 4; nt++) mma_bf16(acc[mt][nt], af, &bl[2 * nt]);
                ldmx4(af, aaddr + MATB);
#pragma unroll
                for (int nt = 0; nt < 4; nt++) mma_bf16(acc[mt][nt], af, &bh[2 * nt]);
            }
        }
    };

    LOAD(0);
    STORE(0);
    __syncthreads();
#pragma unroll 1
    for (int kt = 0; kt < 8; kt++) {
        if (kt + 1 < 8) LOAD(kt + 1);
        COMPUTE(kt & 1);
        if (kt + 1 < 8) {
            STORE((kt + 1) & 1);
            __syncthreads();
        }
    }

    float* C = g_corr + (size_t)bt * 512 * 1024;
    int mrow = n0 + wm * 64 + (lane >> 2);
    int cbase = hw0 + wn * 32 + 2 * (lane & 3);
#pragma unroll
    for (int mt = 0; mt < 4; mt++) {
#pragma unroll
        for (int nt = 0; nt < 4; nt++) {
            int col = cbase + nt * 8;
            int r0 = mrow + mt * 16;
            float2 o0, o1;
            o0.x = acc[mt][nt][0] * 0.0625f;
            o0.y = acc[mt][nt][1] * 0.0625f;
            o1.x = acc[mt][nt][2] * 0.0625f;
            o1.y = acc[mt][nt][3] * 0.0625f;
            *reinterpret_cast<float2*>(C + (size_t)r0 * 1024 + col) = o0;
            *reinterpret_cast<float2*>(C + (size_t)(r0 + 8) * 1024 + col) = o1;
        }
    }
}

// ---------------------------------------------------------------------------
// Bilinear feature sampling at query points.
// ---------------------------------------------------------------------------
__global__ void __launch_bounds__(256) sample_kernel(const float* __restrict__ qp)
{
    int bn = blockIdx.x;
    float q0 = qp[bn * 3 + 0];
    float q1 = qp[bn * 3 + 1];
    float q2 = qp[bn * 3 + 2];

    int t = (int)(q0 * 23.0f);
    t = min(max(t, 0), 23);
    float yf = q1 * 31.0f;
    float xf = q2 * 31.0f;
    int y0 = min(max((int)floorf(yf), 0), 31);
    int y1 = min(y0 + 1, 31);
    int x0 = min(max((int)floorf(xf), 0), 31);
    int x1 = min(x0 + 1, 31);
    float wy1 = yf - (float)y0, wy0 = 1.0f - wy1;
    float wx1 = xf - (float)x0, wx0 = 1.0f - wx1;

    int b = bn >> 9;
    const float* f = g_feat3 + (size_t)(b * 24 + t) * 1024 * 256;
    int c = threadIdx.x;
    float f00 = f[(size_t)(y0 * 32 + x0) * 256 + c];
    float f01 = f[(size_t)(y0 * 32 + x1) * 256 + c];
    float f10 = f[(size_t)(y1 * 32 + x0) * 256 + c];
    float f11 = f[(size_t)(y1 * 32 + x1) * 256 + c];
    float f0 = f00 * wx0 + f01 * wx1;
    float f1 = f10 * wx0 + f11 * wx1;
    g_q[(size_t)bn * 256 + c] = f0 * wy0 + f1 * wy1;
}

// ---------------------------------------------------------------------------
// Fused softmax(corr*10) expectation + occlusion.
// ---------------------------------------------------------------------------
__global__ void __launch_bounds__(256) finalize_kernel(float* __restrict__ out)
{
    int gwarp = (blockIdx.x * 256 + threadIdx.x) >> 5;
    int lane  = threadIdx.x & 31;

    const float* c = g_corr + (size_t)gwarp * 1024;
    float v[32];
    float m = -1e30f;
#pragma unroll
    for (int i = 0; i < 8; i++) {
        float4 t4 = *reinterpret_cast<const float4*>(&c[i * 128 + lane * 4]);
        v[i * 4 + 0] = t4.x;
        v[i * 4 + 1] = t4.y;
        v[i * 4 + 2] = t4.z;
        v[i * 4 + 3] = t4.w;
        m = fmaxf(m, fmaxf(fmaxf(t4.x, t4.y), fmaxf(t4.z, t4.w)));
    }
#pragma unroll
    for (int o = 16; o > 0; o >>= 1)
        m = fmaxf(m, __shfl_xor_sync(0xffffffffu, m, o));

    float s = 0.0f, sx = 0.0f, sy = 0.0f;
#pragma unroll
    for (int i = 0; i < 8; i++) {
#pragma unroll
        for (int j = 0; j < 4; j++) {
            int idx = i * 128 + lane * 4 + j;
            float e = __expf(10.0f * (v[i * 4 + j] - m));
            s  += e;
            sx += e * (float)(idx & 31);
            sy += e * (float)(idx >> 5);
        }
    }
#pragma unroll
    for (int o = 16; o > 0; o >>= 1) {
        s  += __shfl_xor_sync(0xffffffffu, s, o);
        sx += __shfl_xor_sync(0xffffffffu, sx, o);
        sy += __shfl_xor_sync(0xffffffffu, sy, o);
    }

    if (lane == 0) {
        int bt = gwarp >> 9;
        int n  = gwarp & 511;
        int b  = bt / 24;
        int t  = bt - b * 24;
        int o  = (b * 512 + n) * 24 + t;
        float inv = 8.0f / s;
        out[2 * o + 0] = sx * inv;
        out[2 * o + 1] = sy * inv;
        out[2 * 24576 + o] = 1.0f / (1.0f + __expf(m));
    }
}

// ---------------------------------------------------------------------------
// Launch
// ---------------------------------------------------------------------------
extern "C" void kernel_launch(void* const* d_in, const int* in_sizes, int n_in,
                              void* d_out, int out_size)
{
    const float* video = (const float*)d_in[0];
    const float* qp    = (const float*)d_in[1];
    const float* w1    = (const float*)d_in[2];
    const float* b1    = (const float*)d_in[3];
    const float* w2    = (const float*)d_in[4];
    const float* b2    = (const float*)d_in[5];
    const float* w3    = (const float*)d_in[6];
    const float* b3    = (const float*)d_in[7];

    float *f1, *f2, *f3, *wt2, *wt3;
    cudaGetSymbolAddress((void**)&f1, g_feat1);
    cudaGetSymbolAddress((void**)&f2, g_feat2);
    cudaGetSymbolAddress((void**)&f3, g_feat3);
    cudaGetSymbolAddress((void**)&wt2, g_wt2);
    cudaGetSymbolAddress((void**)&wt3, g_wt3);

    cudaFuncSetAttribute((const void*)conv_mma_kernel<64, 128, 128, 128, 64, 64>,
                         cudaFuncAttributeMaxDynamicSharedMemorySize, DSMEM);
    cudaFuncSetAttribute((const void*)conv_mma_kernel<128, 256, 64, 64, 32, 32>,
                         cudaFuncAttributeMaxDynamicSharedMemorySize, DSMEM);
    cudaFuncSetAttribute((const void*)corr_mma_kernel,
                         cudaFuncAttributeMaxDynamicSharedMemorySize, DSMEM);

    // weight transposes (tiny)
    transpose_w_kernel<<<(576 * 128 + 255) / 256, 256>>>(w2, wt2, 576, 128);
    transpose_w_kernel<<<(1152 * 256 + 255) / 256, 256>>>(w3, wt3, 1152, 256);

    // conv1: fp32 direct
    conv1_kernel<<<6144, 128>>>(video, w1, b1);

    // conv2: 196608 px / 128 = 1536 tiles, N=128
    conv_mma_kernel<64, 128, 128, 128, 64, 64>
        <<<dim3(1536, 1, 1), 256, DSMEM>>>(f1, wt2, b2, f2);

    // conv3: 49152 px / 128 = 384 tiles, 2 N-chunks
    conv_mma_kernel<128, 256, 64, 64, 32, 32>
        <<<dim3(384, 2, 1), 256, DSMEM>>>(f2, wt3, b3, f3);

    // feature sampling
    sample_kernel<<<1024, 256>>>(qp);

    // correlation GEMM: 8 hw-tiles x 4 n-tiles x 48 bt
    corr_mma_kernel<<<dim3(8, 4, 48), 256, DSMEM>>>();

    // softmax + expectation + occlusion
    finalize_kernel<<<3072, 256>>>((float*)d_out);
}